// round 3
// baseline (speedup 1.0000x reference)
#include <cuda_runtime.h>
#include <cstdint>

// ============================================================================
// CRF token loss (ModernBertTokenCRF): B=512, T=2048, L=37
// loss = -( sum_b [num_b - denom_b] ) / n_tok
//   num_b   = label path score (start + sum masked (trans+emit) + end)
//   denom_b = forward-algorithm log partition function
//
// Forward pass in LINEAR domain:
//   q_t[j] = (sum_i q_{t-1}[i] * M[i,j]) * exp(emit_t[j]),  M = exp(trans)
//   alpha_t = log(q_t) + ktot*ln2   (renorm each step by 2^-k, k from exp(q[0]))
// ============================================================================

#define LSTATE 37
#define TLEN   2048
#define BATCH  512
#define LP     40       // padded state dim (8B-aligned pairs, zero padding)
#define IPAIRS 19       // ceil(38/2) i-pairs (i=37 is zero padding)
#define PF     8        // emission prefetch depth (hide ~600cyc DRAM latency)

__device__ float g_MexpT[LP * LP];   // [j][i] = exp(trans[i][j]), zero-padded
__device__ float g_num[BATCH];
__device__ float g_denom[BATCH];
__device__ int   g_ntok;

// ---------------------------------------------------------------------------
// Kernel A: precompute exp(transitions) transposed+padded; zero token counter
// ---------------------------------------------------------------------------
__global__ void prep_kernel(const float* __restrict__ trans) {
    int tid = threadIdx.x;
    if (tid == 0) g_ntok = 0;
    for (int x = tid; x < LP * LP; x += blockDim.x) {
        int j = x / LP, i = x % LP;
        g_MexpT[x] = (i < LSTATE && j < LSTATE) ? expf(trans[i * LSTATE + j]) : 0.0f;
    }
}

// ---------------------------------------------------------------------------
// Kernel B: numerator (one warp per batch) + n_tok accumulation
// ---------------------------------------------------------------------------
__global__ void num_kernel(const float* __restrict__ em,
                           const float* __restrict__ trans,
                           const float* __restrict__ startt,
                           const float* __restrict__ endt,
                           const int*   __restrict__ labels,
                           const int*   __restrict__ mask) {
    int wid  = threadIdx.x >> 5;
    int lane = threadIdx.x & 31;
    int b = blockIdx.x * (blockDim.x >> 5) + wid;
    if (b >= BATCH) return;

    const int*   lb = labels + (size_t)b * TLEN;
    const int*   mk = mask   + (size_t)b * TLEN;
    const float* eb = em     + (size_t)b * TLEN * LSTATE;

    float acc = 0.0f;
    int   msum = 0;
    for (int t = lane; t < TLEN; t += 32) {
        int lt = lb[t];
        int m  = mk[t];
        msum += m;
        if (t == 0) {
            acc += startt[lt] + eb[lt];
        } else if (m) {
            int lp = lb[t - 1];
            acc += trans[lp * LSTATE + lt] + eb[(size_t)t * LSTATE + lt];
        }
    }
    #pragma unroll
    for (int o = 16; o; o >>= 1) {
        acc  += __shfl_down_sync(0xffffffffu, acc,  o);
        msum += __shfl_down_sync(0xffffffffu, msum, o);
    }
    if (lane == 0) {
        int len  = msum;
        int last = lb[len - 1];
        g_num[b] = acc + endt[last];
        atomicAdd(&g_ntok, msum);
    }
}

// ---------------------------------------------------------------------------
// Kernel C: forward algorithm (denominator). 2 batches per 128-thread block
// (one batch per 64 threads -> warps land on all 4 SMSPs). Thread j owns state
// column j; reduction dim packed as f32x2 i-pairs; q double-buffered in smem
// (1 __syncthreads per step); per-step power-of-2 renorm from q[0] exponent;
// 8-deep emission register prefetch pipeline.
// ---------------------------------------------------------------------------
__global__ void __launch_bounds__(128)
fwd_kernel(const float* __restrict__ em,
           const float* __restrict__ startt,
           const float* __restrict__ endt,
           const int*   __restrict__ mask) {
    __shared__ __align__(16) float q_sm[2][2][LP];   // [local batch][buf][state]

    int tid   = threadIdx.x;
    int local = tid >> 6;        // 0 or 1: batch within block
    int j     = tid & 63;        // state column (active j < 37)
    int b     = blockIdx.x * 2 + local;

    const float* eb = em   + (size_t)b * TLEN * LSTATE;
    const int*   mk = mask + (size_t)b * TLEN;

    // zero smem (padding states must stay 0 forever)
    for (int x = tid; x < 2 * 2 * LP; x += 128) ((float*)q_sm)[x] = 0.0f;

    // M column (pairs over i) into registers: Mc[i2] = {M[2i2][j], M[2i2+1][j]}
    unsigned long long Mc[IPAIRS];
    if (j < LSTATE) {
        const unsigned long long* col =
            (const unsigned long long*)(g_MexpT + j * LP);
        #pragma unroll
        for (int i2 = 0; i2 < IPAIRS; i2++) Mc[i2] = col[i2];
    }
    __syncthreads();

    // t = 0 init: q0[j] = exp(start[j] + emit0[j]) into buf 0
    if (j < LSTATE) {
        q_sm[local][0][j] = __expf(startt[j] + eb[j]);
    }
    int ktot = 0;

    // prime prefetch pipeline for t = 1..PF
    float e_pipe[PF];
    int   m_pipe[PF];
    #pragma unroll
    for (int d = 0; d < PF; d++) {
        int tt = 1 + d;
        e_pipe[d] = (j < LSTATE) ? eb[(size_t)tt * LSTATE + j] : 0.0f;
        m_pipe[d] = mk[tt];
    }
    __syncthreads();

    float* bufs = &q_sm[local][0][0];   // two LP-float buffers

    // steps t = 1..TLEN (t == TLEN is a dummy masked step so TLEN % PF == 0)
    for (int t0 = 1; t0 <= TLEN; t0 += PF) {
        #pragma unroll
        for (int u = 0; u < PF; u++) {
            int   t    = t0 + u;
            float eraw = e_pipe[u];
            int   mcur = m_pipe[u];
            // prefetch t + PF
            {
                int tp  = t + PF;
                int tpc = tp < TLEN ? tp : (TLEN - 1);
                e_pipe[u] = (j < LSTATE) ? eb[(size_t)tpc * LSTATE + j] : 0.0f;
                m_pipe[u] = (tp < TLEN) ? mk[tp] : 0;
            }

            const float* qr = bufs + ((t + 1) & 1) * LP;   // read buffer
            float*       qw = bufs + (t & 1) * LP;          // write buffer

            if (j < LSTATE) {
                const unsigned long long* qp = (const unsigned long long*)qr;
                unsigned long long acc0, acc1 = 0ull;
                // i2 = 0 (also yields q[0] for the renorm exponent)
                unsigned long long qv0 = qp[0];
                float q0val = __uint_as_float((unsigned)(qv0 & 0xffffffffu));
                acc0 = 0ull;
                asm("fma.rn.f32x2 %0, %1, %2, %3;"
                    : "=l"(acc0) : "l"(qv0), "l"(Mc[0]), "l"(acc0));
                #pragma unroll
                for (int i2 = 1; i2 < IPAIRS; i2++) {
                    unsigned long long qv = qp[i2];
                    if (i2 & 1)
                        asm("fma.rn.f32x2 %0, %1, %2, %3;"
                            : "=l"(acc1) : "l"(qv), "l"(Mc[i2]), "l"(acc1));
                    else
                        asm("fma.rn.f32x2 %0, %1, %2, %3;"
                            : "=l"(acc0) : "l"(qv), "l"(Mc[i2]), "l"(acc0));
                }
                float s = __uint_as_float((unsigned)(acc0 & 0xffffffffu))
                        + __uint_as_float((unsigned)(acc0 >> 32))
                        + __uint_as_float((unsigned)(acc1 & 0xffffffffu))
                        + __uint_as_float((unsigned)(acc1 >> 32));

                // power-of-2 renorm from q[0]'s exponent (exact)
                unsigned ebits = (__float_as_uint(q0val) >> 23) & 0xffu;
                float scale = __uint_as_float((254u - ebits) << 23);  // 2^-(e-127)
                ktot += (int)ebits - 127;

                float qold = qr[j];
                float qn = (mcur ? s * __expf(eraw) : qold) * scale;
                qw[j] = qn;
            }
            __syncthreads();   // single barrier per step (double-buffered)
        }
    }

    // final buffer after t = TLEN (even) is buf 0; use buf 1 as scratch
    float* fbuf = bufs;        // buf 0
    float* red  = bufs + LP;   // buf 1
    if (j < LSTATE) red[j] = fbuf[j] * __expf(endt[j]);
    __syncthreads();
    if (j == 0) {
        float ssum = 0.0f;
        #pragma unroll
        for (int i = 0; i < LSTATE; i++) ssum += red[i];
        g_denom[b] = (float)((double)ktot * 0.6931471805599453) + logf(ssum);
    }
}

// ---------------------------------------------------------------------------
// Kernel D: final reduction -> scalar loss
// ---------------------------------------------------------------------------
__global__ void finish_kernel(float* __restrict__ out) {
    __shared__ float sm[BATCH];
    int tid = threadIdx.x;
    sm[tid] = g_num[tid] - g_denom[tid];
    __syncthreads();
    #pragma unroll
    for (int s = BATCH / 2; s; s >>= 1) {
        if (tid < s) sm[tid] += sm[tid + s];
        __syncthreads();
    }
    if (tid == 0) {
        int nt = g_ntok;
        if (nt < 1) nt = 1;
        out[0] = -sm[0] / (float)nt;
    }
}

// ---------------------------------------------------------------------------
// Launch
// ---------------------------------------------------------------------------
extern "C" void kernel_launch(void* const* d_in, const int* in_sizes, int n_in,
                              void* d_out, int out_size) {
    const float* em     = (const float*)d_in[0];   // emissions [512,2048,37]
    const float* trans  = (const float*)d_in[1];   // transitions [37,37]
    const float* startt = (const float*)d_in[2];   // start_transitions [37]
    const float* endt   = (const float*)d_in[3];   // end_transitions [37]
    const int*   labels = (const int*)d_in[4];     // labels [512,2048]
    const int*   mask   = (const int*)d_in[5];     // attention_mask [512,2048]

    prep_kernel<<<1, 256>>>(trans);
    num_kernel<<<64, 256>>>(em, trans, startt, endt, labels, mask);
    fwd_kernel<<<BATCH / 2, 128>>>(em, startt, endt, mask);
    finish_kernel<<<1, BATCH>>>((float*)d_out);
}

// round 4
// speedup vs baseline: 1.1400x; 1.1400x over previous
#include <cuda_runtime.h>
#include <cstdint>

// ============================================================================
// CRF token loss (ModernBertTokenCRF): B=512, T=2048, L=37
// loss = -( sum_b [num_b - denom_b] ) / n_tok
//
// fwd pass in linear domain: q_t[j] = exp(emit_t[j]) * sum_i q_{t-1}[i]*M[i,j]
// with M = exp(trans), per-step power-of-2 renorm (exact exponent bookkeeping).
//
// R3: one warp per batch (no __syncthreads in the recurrence), warp-private
// double-buffered q in smem + one __syncwarp per step, exp(emission)
// precomputed in an 8-deep prefetch pipeline, last-block finish reduction.
// ============================================================================

#define LSTATE  37
#define TLEN    2048
#define BATCH   512
#define MSTRIDE 38      // padded i-dim (even -> 8B pairs), M[j][37]=0
#define IPAIRS  19
#define QBUF    40      // per-buffer floats (16B-aligned slices)
#define PF      8
#define FULLMASK 0xffffffffu

__device__ __align__(16) float g_MexpT[LSTATE * MSTRIDE]; // [j][i]=exp(trans[i][j])
__device__ float g_num[BATCH];
__device__ float g_denom[BATCH];
__device__ int   g_msum[BATCH];
__device__ int   g_done;

// ---- f32x2 helpers ---------------------------------------------------------
__device__ __forceinline__ void fma2(unsigned long long& acc,
                                     unsigned long long a, unsigned long long b) {
    asm("fma.rn.f32x2 %0, %1, %2, %0;" : "+l"(acc) : "l"(a), "l"(b));
}
__device__ __forceinline__ unsigned long long add2(unsigned long long a,
                                                   unsigned long long b) {
    unsigned long long c;
    asm("add.rn.f32x2 %0, %1, %2;" : "=l"(c) : "l"(a), "l"(b));
    return c;
}
__device__ __forceinline__ float lo32(unsigned long long v) {
    return __uint_as_float((unsigned)v);
}
__device__ __forceinline__ float hi32(unsigned long long v) {
    return __uint_as_float((unsigned)(v >> 32));
}

// ---------------------------------------------------------------------------
// Kernel 1: numerator per batch (one warp each) + prep (block 0) 
// ---------------------------------------------------------------------------
__global__ void num_kernel(const float* __restrict__ em,
                           const float* __restrict__ trans,
                           const float* __restrict__ startt,
                           const float* __restrict__ endt,
                           const int*   __restrict__ labels,
                           const int*   __restrict__ mask) {
    // block 0: build exp(transitions) transposed + padded; reset g_done
    if (blockIdx.x == 0) {
        for (int x = threadIdx.x; x < LSTATE * MSTRIDE; x += blockDim.x) {
            int j = x / MSTRIDE, i = x % MSTRIDE;
            g_MexpT[x] = (i < LSTATE) ? expf(trans[i * LSTATE + j]) : 0.0f;
        }
        if (threadIdx.x == 0) g_done = 0;
    }

    int wid  = threadIdx.x >> 5;
    int lane = threadIdx.x & 31;
    int b = blockIdx.x * (blockDim.x >> 5) + wid;
    if (b >= BATCH) return;

    const int*   lb = labels + (size_t)b * TLEN;
    const int*   mk = mask   + (size_t)b * TLEN;
    const float* eb = em     + (size_t)b * TLEN * LSTATE;

    float acc = 0.0f;
    int   msum = 0;
    for (int t = lane; t < TLEN; t += 32) {
        int lt = lb[t];
        int m  = mk[t];
        msum += m;
        if (t == 0) {
            acc += startt[lt] + eb[lt];
        } else if (m) {
            int lp = lb[t - 1];
            acc += trans[lp * LSTATE + lt] + eb[(size_t)t * LSTATE + lt];
        }
    }
    #pragma unroll
    for (int o = 16; o; o >>= 1) {
        acc  += __shfl_down_sync(FULLMASK, acc,  o);
        msum += __shfl_down_sync(FULLMASK, msum, o);
    }
    if (lane == 0) {
        int last = lb[msum - 1];
        g_num[b]  = acc + endt[last];
        g_msum[b] = msum;
    }
}

// ---------------------------------------------------------------------------
// Kernel 2: forward recurrence, one warp per batch, + fused final reduction
// ---------------------------------------------------------------------------
__global__ void __launch_bounds__(128, 1)
fwd_kernel(const float* __restrict__ em,
           const float* __restrict__ startt,
           const float* __restrict__ endt,
           const int*   __restrict__ mask,
           float* __restrict__ out) {
    __shared__ __align__(16) float q_sm[4][2][QBUF];
    __shared__ float r_acc[4];
    __shared__ int   r_nt[4];
    __shared__ int   isLast;

    int lane = threadIdx.x & 31;
    int w    = threadIdx.x >> 5;
    int b    = blockIdx.x * 4 + w;

    const float* eb = em   + (size_t)b * TLEN * LSTATE;
    const int*   mk = mask + (size_t)b * TLEN;

    int j  = lane;                               // primary column (0..31)
    int j2 = (lane < 5) ? (32 + lane) : 36;      // secondary column (clamped)

    // M columns into registers as i-pairs
    unsigned long long Mp[IPAIRS], Ms[IPAIRS];
    {
        const unsigned long long* cp =
            (const unsigned long long*)(g_MexpT + j  * MSTRIDE);
        const unsigned long long* cs =
            (const unsigned long long*)(g_MexpT + j2 * MSTRIDE);
        #pragma unroll
        for (int k = 0; k < IPAIRS; k++) { Mp[k] = cp[k]; Ms[k] = cs[k]; }
    }

    float* buf0 = &q_sm[w][0][0];
    float* buf1 = &q_sm[w][1][0];

    // zero pad slots (i=37..39) in both buffers; they are never rewritten
    if (lane < 3) { buf0[37 + lane] = 0.0f; buf1[37 + lane] = 0.0f; }

    // t=0 init into buf0
    buf0[j] = __expf(startt[j] + eb[j]);
    if (lane < 5) buf0[32 + lane] = __expf(startt[32 + lane] + eb[32 + lane]);

    // prime prefetch pipeline (steps t=1..PF), exp precomputed here
    float ep[PF], es[PF];
    int   mp[PF];
    #pragma unroll
    for (int d = 0; d < PF; d++) {
        int tt = 1 + d;
        ep[d] = __expf(eb[(size_t)tt * LSTATE + j]);
        es[d] = __expf(eb[(size_t)tt * LSTATE + j2]);
        mp[d] = mk[tt];
    }

    int ktot = 0;

    // steps t = 1..TLEN  (t=TLEN is a dummy masked step; TLEN % PF == 0)
    for (int t0 = 1; t0 <= TLEN; t0 += PF) {
        #pragma unroll
        for (int u = 0; u < PF; u++) {
            int   t    = t0 + u;
            float ePv  = ep[u];
            float eSv  = es[u];
            int   mcur = mp[u];
            // refill prefetch for t + PF
            {
                int tp  = t + PF;
                int tpc = (tp < TLEN) ? tp : (TLEN - 1);
                ep[u] = __expf(eb[(size_t)tpc * LSTATE + j]);
                es[u] = __expf(eb[(size_t)tpc * LSTATE + j2]);
                mp[u] = (tp < TLEN) ? mk[tp] : 0;
            }

            // t0 is always odd: parity of t == parity of (u+1) -> compile-time
            float* bufr = (u & 1) ? buf1 : buf0;          // holds q_{t-1}
            float* bufw = (u & 1) ? buf0 : buf1;          // receives q_t

            __syncwarp();   // prior step's stores visible

            const unsigned long long* qp64 = (const unsigned long long*)bufr;
            unsigned long long qv0 = qp64[0];
            float q0 = lo32(qv0);

            unsigned long long a0 = 0, a1 = 0, a2 = 0, a3 = 0;
            unsigned long long s0 = 0, s1 = 0, s2 = 0, s3 = 0;
            fma2(a0, qv0, Mp[0]);  fma2(s0, qv0, Ms[0]);
            #pragma unroll
            for (int k = 1; k < IPAIRS; k++) {
                unsigned long long qv = qp64[k];
                switch (k & 3) {
                    case 0: fma2(a0, qv, Mp[k]); fma2(s0, qv, Ms[k]); break;
                    case 1: fma2(a1, qv, Mp[k]); fma2(s1, qv, Ms[k]); break;
                    case 2: fma2(a2, qv, Mp[k]); fma2(s2, qv, Ms[k]); break;
                    default: fma2(a3, qv, Mp[k]); fma2(s3, qv, Ms[k]); break;
                }
            }
            unsigned long long ac = add2(add2(a0, a1), add2(a2, a3));
            unsigned long long sc = add2(add2(s0, s1), add2(s2, s3));
            float spri = lo32(ac) + hi32(ac);
            float ssec = lo32(sc) + hi32(sc);

            // power-of-2 renorm from q[0]'s exponent (exact)
            unsigned ebits = (__float_as_uint(q0) >> 23) & 0xffu;
            float scale = __uint_as_float((254u - ebits) << 23);  // 2^-(e-127)
            ktot += (int)ebits - 127;

            float qold  = bufr[j];
            float qsold = bufr[j2];
            float qn  = (mcur ? spri * ePv : qold)  * scale;
            float qsn = (mcur ? ssec * eSv : qsold) * scale;

            bufw[j] = qn;
            if (lane < 5) bufw[32 + lane] = qsn;
        }
    }
    __syncwarp();

    // t=TLEN (even, u=7) wrote buf0: final state there
    {
        float v = buf0[j] * __expf(endt[j]);
        if (lane < 5) v += buf0[32 + lane] * __expf(endt[32 + lane]);
        #pragma unroll
        for (int o = 16; o; o >>= 1) v += __shfl_down_sync(FULLMASK, v, o);
        if (lane == 0)
            g_denom[b] = (float)((double)ktot * 0.6931471805599453) + logf(v);
    }

    // ---- fused finish: last block reduces everything ----
    __threadfence();
    __syncthreads();
    if (threadIdx.x == 0)
        isLast = (atomicAdd(&g_done, 1) == (int)gridDim.x - 1);
    __syncthreads();

    if (isLast) {
        __threadfence();
        float acc = 0.0f;
        int   nt  = 0;
        for (int i = threadIdx.x; i < BATCH; i += 128) {
            acc += g_num[i] - g_denom[i];
            nt  += g_msum[i];
        }
        #pragma unroll
        for (int o = 16; o; o >>= 1) {
            acc += __shfl_down_sync(FULLMASK, acc, o);
            nt  += __shfl_down_sync(FULLMASK, nt,  o);
        }
        if (lane == 0) { r_acc[w] = acc; r_nt[w] = nt; }
        __syncthreads();
        if (threadIdx.x == 0) {
            float tot = r_acc[0] + r_acc[1] + r_acc[2] + r_acc[3];
            int   n   = r_nt[0] + r_nt[1] + r_nt[2] + r_nt[3];
            if (n < 1) n = 1;
            out[0] = -tot / (float)n;
        }
    }
}

// ---------------------------------------------------------------------------
// Launch
// ---------------------------------------------------------------------------
extern "C" void kernel_launch(void* const* d_in, const int* in_sizes, int n_in,
                              void* d_out, int out_size) {
    const float* em     = (const float*)d_in[0];   // emissions [512,2048,37]
    const float* trans  = (const float*)d_in[1];   // transitions [37,37]
    const float* startt = (const float*)d_in[2];   // start_transitions [37]
    const float* endt   = (const float*)d_in[3];   // end_transitions [37]
    const int*   labels = (const int*)d_in[4];     // labels [512,2048]
    const int*   mask   = (const int*)d_in[5];     // attention_mask [512,2048]

    num_kernel<<<64, 256>>>(em, trans, startt, endt, labels, mask);
    fwd_kernel<<<BATCH / 4, 128>>>(em, startt, endt, mask, (float*)d_out);
}

// round 5
// speedup vs baseline: 1.1409x; 1.0008x over previous
#include <cuda_runtime.h>
#include <cstdint>

// ============================================================================
// CRF token loss (ModernBertTokenCRF): B=512, T=2048, L=37
// loss = -( sum_b [num_b - denom_b] ) / n_tok
//
// Forward pass in linear domain: q_t[j] = exp(emit_t[j]) * sum_i q_{t-1}[i]*M[i,j]
// with M = exp(trans); per-step exact power-of-2 renorm from q[0]'s exponent.
//
// R4: TWO warps per batch (cols 0-18 / 19-36, one column per lane -> no
// wasted secondary FMA stream), per-batch 64-thread named barrier, q double-
// buffered in smem, exp(emission) precomputed 8 steps ahead.
// 128 blocks x 256 threads = 1024 warps = 2/SMSP, all 512 chains co-resident.
// ============================================================================

#define LSTATE  37
#define TLEN    2048
#define BATCH   512
#define MSTRIDE 38      // padded i-dim (even -> 8B pairs), M[j][37]=0
#define IPAIRS  19
#define QBUF    40
#define PF      8
#define FULLMASK 0xffffffffu

__device__ __align__(16) float g_MexpT[LSTATE * MSTRIDE]; // [j][i]=exp(trans[i][j])
__device__ float g_num[BATCH];
__device__ float g_denom[BATCH];
__device__ int   g_msum[BATCH];
__device__ int   g_done;

// ---- f32x2 helpers ---------------------------------------------------------
__device__ __forceinline__ void fma2(unsigned long long& acc,
                                     unsigned long long a, unsigned long long b) {
    asm("fma.rn.f32x2 %0, %1, %2, %0;" : "+l"(acc) : "l"(a), "l"(b));
}
__device__ __forceinline__ unsigned long long add2(unsigned long long a,
                                                   unsigned long long b) {
    unsigned long long c;
    asm("add.rn.f32x2 %0, %1, %2;" : "=l"(c) : "l"(a), "l"(b));
    return c;
}
__device__ __forceinline__ float lo32(unsigned long long v) {
    return __uint_as_float((unsigned)v);
}
__device__ __forceinline__ float hi32(unsigned long long v) {
    return __uint_as_float((unsigned)(v >> 32));
}

// ---------------------------------------------------------------------------
// Kernel 1: numerator per batch (one warp each) + prep (block 0)
// ---------------------------------------------------------------------------
__global__ void num_kernel(const float* __restrict__ em,
                           const float* __restrict__ trans,
                           const float* __restrict__ startt,
                           const float* __restrict__ endt,
                           const int*   __restrict__ labels,
                           const int*   __restrict__ mask) {
    if (blockIdx.x == 0) {
        for (int x = threadIdx.x; x < LSTATE * MSTRIDE; x += blockDim.x) {
            int j = x / MSTRIDE, i = x % MSTRIDE;
            g_MexpT[x] = (i < LSTATE) ? expf(trans[i * LSTATE + j]) : 0.0f;
        }
        if (threadIdx.x == 0) g_done = 0;
    }

    int wid  = threadIdx.x >> 5;
    int lane = threadIdx.x & 31;
    int b = blockIdx.x * (blockDim.x >> 5) + wid;
    if (b >= BATCH) return;

    const int*   lb = labels + (size_t)b * TLEN;
    const int*   mk = mask   + (size_t)b * TLEN;
    const float* eb = em     + (size_t)b * TLEN * LSTATE;

    float acc = 0.0f;
    int   msum = 0;
    for (int t = lane; t < TLEN; t += 32) {
        int lt = lb[t];
        int m  = mk[t];
        msum += m;
        if (t == 0) {
            acc += startt[lt] + eb[lt];
        } else if (m) {
            int lp = lb[t - 1];
            acc += trans[lp * LSTATE + lt] + eb[(size_t)t * LSTATE + lt];
        }
    }
    #pragma unroll
    for (int o = 16; o; o >>= 1) {
        acc  += __shfl_down_sync(FULLMASK, acc,  o);
        msum += __shfl_down_sync(FULLMASK, msum, o);
    }
    if (lane == 0) {
        int last = lb[msum - 1];
        g_num[b]  = acc + endt[last];
        g_msum[b] = msum;
    }
}

// ---------------------------------------------------------------------------
// Kernel 2: forward recurrence, 2 warps per batch, + fused final reduction
// ---------------------------------------------------------------------------
__global__ void __launch_bounds__(256, 1)
fwd_kernel(const float* __restrict__ em,
           const float* __restrict__ startt,
           const float* __restrict__ endt,
           const int*   __restrict__ mask,
           float* __restrict__ out) {
    __shared__ __align__(16) float q_sm[4][2][QBUF];  // [batch-in-block][buf][state]
    __shared__ float r_part[4][2];
    __shared__ float r_acc[8];
    __shared__ int   r_nt[8];
    __shared__ int   isLast;

    int tid  = threadIdx.x;
    int lane = tid & 31;
    int wid  = tid >> 5;           // 0..7
    int g    = wid >> 1;           // batch within block: 0..3
    int w    = wid & 1;            // warp within batch: 0 or 1
    int b    = blockIdx.x * 4 + g;
    int barid = 1 + g;             // named barrier id per batch

    const float* eb = em   + (size_t)b * TLEN * LSTATE;
    const int*   mk = mask + (size_t)b * TLEN;

    // column ownership: warp0 -> 0..18 (lane<19), warp1 -> 19..36 (lane<18)
    int  col    = w ? (19 + lane) : lane;
    bool active = w ? (lane < 18) : (lane < 19);
    int  colc   = (col < LSTATE) ? col : (LSTATE - 1);   // clamped for loads

    // M column (i-pairs) into registers
    unsigned long long Mp[IPAIRS];
    {
        const unsigned long long* cp =
            (const unsigned long long*)(g_MexpT + colc * MSTRIDE);
        #pragma unroll
        for (int k = 0; k < IPAIRS; k++) Mp[k] = cp[k];
    }

    float* buf0 = &q_sm[g][0][0];
    float* buf1 = &q_sm[g][1][0];

    // zero pad slots (37..39) in both buffers (never rewritten)
    if (w == 0 && lane >= 19 && lane < 22) {
        buf0[18 + lane] = 0.0f;   // 37,38,39
        buf1[18 + lane] = 0.0f;
    }

    // t = 0 init into buf0
    if (active) buf0[col] = __expf(startt[col] + eb[col]);

    // prime prefetch pipeline (steps t=1..PF); exp precomputed here
    float ep[PF];
    int   mp[PF];
    #pragma unroll
    for (int d = 0; d < PF; d++) {
        int tt = 1 + d;
        ep[d] = __expf(eb[(size_t)tt * LSTATE + colc]);
        mp[d] = mk[tt];
    }

    int ktot = 0;
    __syncthreads();

    // steps t = 1..TLEN  (t=TLEN is a dummy masked step; TLEN % PF == 0)
    for (int t0 = 1; t0 <= TLEN; t0 += PF) {
        #pragma unroll
        for (int u = 0; u < PF; u++) {
            int   t    = t0 + u;
            float ev   = ep[u];
            int   mcur = mp[u];
            // refill prefetch for t + PF
            {
                int tp  = t + PF;
                int tpc = (tp < TLEN) ? tp : (TLEN - 1);
                ep[u] = __expf(eb[(size_t)tpc * LSTATE + colc]);
                mp[u] = (tp < TLEN) ? mk[tp] : 0;
            }

            // t0 odd: u even -> t odd -> read buf0, write buf1 (compile-time)
            float* bufr = (u & 1) ? buf1 : buf0;
            float* bufw = (u & 1) ? buf0 : buf1;

            // per-batch barrier (both warps of this batch, 64 threads)
            asm volatile("bar.sync %0, %1;" :: "r"(barid), "r"(64) : "memory");

            const unsigned long long* qp64 = (const unsigned long long*)bufr;
            unsigned long long qv0 = qp64[0];
            float q0 = lo32(qv0);

            unsigned long long a0 = 0, a1 = 0, a2 = 0, a3 = 0;
            fma2(a0, qv0, Mp[0]);
            #pragma unroll
            for (int k = 1; k < IPAIRS; k++) {
                unsigned long long qv = qp64[k];
                switch (k & 3) {
                    case 0:  fma2(a0, qv, Mp[k]); break;
                    case 1:  fma2(a1, qv, Mp[k]); break;
                    case 2:  fma2(a2, qv, Mp[k]); break;
                    default: fma2(a3, qv, Mp[k]); break;
                }
            }
            unsigned long long ac = add2(add2(a0, a1), add2(a2, a3));
            float s = lo32(ac) + hi32(ac);

            // exact power-of-2 renorm from q[0]'s exponent
            unsigned ebits = (__float_as_uint(q0) >> 23) & 0xffu;
            float scale = __uint_as_float((254u - ebits) << 23);  // 2^-(e-127)
            ktot += (int)ebits - 127;

            float qold = bufr[colc];
            float qn   = (mcur ? s * ev : qold) * scale;
            if (active) bufw[col] = qn;
        }
    }
    asm volatile("bar.sync %0, %1;" :: "r"(barid), "r"(64) : "memory");

    // final state in buf0 (t=TLEN even). Per-warp partial of sum_j q[j]*exp(end_j)
    {
        float v = active ? buf0[colc] * __expf(endt[colc]) : 0.0f;
        #pragma unroll
        for (int o = 16; o; o >>= 1) v += __shfl_down_sync(FULLMASK, v, o);
        if (lane == 0) r_part[g][w] = v;
    }
    asm volatile("bar.sync %0, %1;" :: "r"(barid), "r"(64) : "memory");
    if (w == 0 && lane == 0) {
        float ssum = r_part[g][0] + r_part[g][1];
        g_denom[b] = (float)((double)ktot * 0.6931471805599453) + logf(ssum);
    }

    // ---- fused finish: last block reduces everything ----
    __threadfence();
    __syncthreads();
    if (tid == 0)
        isLast = (atomicAdd(&g_done, 1) == (int)gridDim.x - 1);
    __syncthreads();

    if (isLast) {
        __threadfence();
        float acc = 0.0f;
        int   nt  = 0;
        for (int i = tid; i < BATCH; i += 256) {
            acc += g_num[i] - g_denom[i];
            nt  += g_msum[i];
        }
        #pragma unroll
        for (int o = 16; o; o >>= 1) {
            acc += __shfl_down_sync(FULLMASK, acc, o);
            nt  += __shfl_down_sync(FULLMASK, nt,  o);
        }
        if (lane == 0) { r_acc[wid] = acc; r_nt[wid] = nt; }
        __syncthreads();
        if (tid == 0) {
            float tot = 0.0f; int n = 0;
            #pragma unroll
            for (int k = 0; k < 8; k++) { tot += r_acc[k]; n += r_nt[k]; }
            if (n < 1) n = 1;
            out[0] = -tot / (float)n;
        }
    }
}

// ---------------------------------------------------------------------------
// Launch
// ---------------------------------------------------------------------------
extern "C" void kernel_launch(void* const* d_in, const int* in_sizes, int n_in,
                              void* d_out, int out_size) {
    const float* em     = (const float*)d_in[0];   // emissions [512,2048,37]
    const float* trans  = (const float*)d_in[1];   // transitions [37,37]
    const float* startt = (const float*)d_in[2];   // start_transitions [37]
    const float* endt   = (const float*)d_in[3];   // end_transitions [37]
    const int*   labels = (const int*)d_in[4];     // labels [512,2048]
    const int*   mask   = (const int*)d_in[5];     // attention_mask [512,2048]

    num_kernel<<<64, 256>>>(em, trans, startt, endt, labels, mask);
    fwd_kernel<<<BATCH / 4, 256>>>(em, startt, endt, mask, (float*)d_out);
}